// round 14
// baseline (speedup 1.0000x reference)
#include <cuda_runtime.h>
#include <math.h>

// Problem dims (fixed by setup_inputs)
constexpr int B = 8, H = 384, W = 768;
constexpr int HW = H * W;              // 294912
constexpr int NPIX = B * HW;           // 2359296

// Accumulators: 0 photo_fw, 1 photo_bw, 2 census_fw, 3 census_bw, 4 mask_fw_sum, 5 mask_bw_sum
// Zero-initialized at module load; the last census block re-zeroes after reading.
__device__ double g_acc[6];
__device__ unsigned int g_ctr;   // census block completion counter (zero-init)

// Scratch gray maps (intensity*255) and backward mask
__device__ float g_g1[NPIX];    // gray(img1)*255
__device__ float g_g2[NPIX];    // gray(img2)*255
__device__ float g_g1w[NPIX];   // gray(warp(img1, flow_bw))*255
__device__ float g_g2w[NPIX];   // gray(warp(img2, flow_fw))*255
__device__ float g_maskbw[NPIX];

struct Bilin {
    int i00, i01, i10, i11;
    float w00, w01, w10, w11;
};

__device__ __forceinline__ Bilin make_bilin(float fx, float fy, int x, int y) {
    float gx = fminf(fmaxf(fx + (float)x, 0.0f), (float)(W - 1));
    float gy = fminf(fmaxf(fy + (float)y, 0.0f), (float)(H - 1));
    float x0 = floorf(gx), y0 = floorf(gy);
    float wx = gx - x0, wy = gy - y0;
    int x0i = (int)x0, y0i = (int)y0;
    int x1i = min(x0i + 1, W - 1);
    int y1i = min(y0i + 1, H - 1);
    Bilin b;
    b.i00 = y0i * W + x0i;
    b.i01 = y0i * W + x1i;
    b.i10 = y1i * W + x0i;
    b.i11 = y1i * W + x1i;
    float ix = 1.0f - wx, iy = 1.0f - wy;
    b.w00 = ix * iy; b.w01 = wx * iy; b.w10 = ix * wy; b.w11 = wx * wy;
    return b;
}

__device__ __forceinline__ float samp(const float* __restrict__ p, const Bilin& bl) {
    return bl.w00 * __ldg(p + bl.i00) + bl.w01 * __ldg(p + bl.i01)
         + bl.w10 * __ldg(p + bl.i10) + bl.w11 * __ldg(p + bl.i11);
}

__device__ __forceinline__ float warp_reduce(float v) {
    #pragma unroll
    for (int o = 16; o > 0; o >>= 1) v += __shfl_down_sync(0xFFFFFFFFu, v, o);
    return v;
}

// FMA-pipe reciprocal: bit-hack seed + 2 Newton iterations.
// For x in (0.1, 5.1] rel err ~1e-6. Keeps the MUFU pipe free.
__device__ __forceinline__ float rcp_fma(float x) {
    float r = __uint_as_float(0x7EF477D5u - __float_as_uint(x));
    r = r * (2.0f - x * r);
    r = r * (2.0f - x * r);
    return r;
}

// Per-pixel: occ fw/bw, photometric loss partials, gray maps (round-7 form)
__global__ void __launch_bounds__(256) k_main(const float* __restrict__ img1,
                                              const float* __restrict__ img2,
                                              const float* __restrict__ ffw,
                                              const float* __restrict__ fbw,
                                              float* __restrict__ out) {
    int i = blockIdx.x * blockDim.x + threadIdx.x;   // grid sized exactly
    int b = i / HW;
    int r = i - b * HW;
    int y = r / W;
    int x = r - y * W;

    const float* f1 = ffw + (size_t)b * 2 * HW;
    const float* f2 = fbw + (size_t)b * 2 * HW;
    float fwx = f1[r],       fwy = f1[HW + r];
    float bwx = f2[r],       bwy = f2[HW + r];

    Bilin bf = make_bilin(fwx, fwy, x, y);
    Bilin bb = make_bilin(bwx, bwy, x, y);

    // occ_fw = compute_occ(flow_fw, flow_bw)
    float bwwx = samp(f2, bf);
    float bwwy = samp(f2 + HW, bf);
    float dx0 = fwx + bwwx, dy0 = fwy + bwwy;
    float mag = dx0 * dx0 + dy0 * dy0;
    float fm  = fwx * fwx + fwy * fwy + bwwx * bwwx + bwwy * bwwy;
    float occf = (mag > fmaf(0.01f, fm, 0.5f)) ? 1.0f : 0.0f;
    out[3 + i] = occf;
    float mfw = 1.0f - occf;

    // occ_bw = compute_occ(flow_bw, flow_fw)
    float fwwx = samp(f1, bb);
    float fwwy = samp(f1 + HW, bb);
    float dx1 = bwx + fwwx, dy1 = bwy + fwwy;
    float mag1 = dx1 * dx1 + dy1 * dy1;
    float fm1  = bwx * bwx + bwy * bwy + fwwx * fwwx + fwwy * fwwy;
    float occb = (mag1 > fmaf(0.01f, fm1, 0.5f)) ? 1.0f : 0.0f;
    float mbw = 1.0f - occb;
    g_maskbw[i] = mbw;

    // image warps + photometric
    const float* i1 = img1 + (size_t)b * 3 * HW;
    const float* i2 = img2 + (size_t)b * 3 * HW;

    float w0 = samp(i2, bf), w1 = samp(i2 + HW, bf), w2 = samp(i2 + 2 * HW, bf);
    float a0 = i1[r], a1 = i1[HW + r], a2 = i1[2 * HW + r];
    float pfw = mfw * (__powf(fabsf(a0 - w0) + 0.01f, 0.4f)
                     + __powf(fabsf(a1 - w1) + 0.01f, 0.4f)
                     + __powf(fabsf(a2 - w2) + 0.01f, 0.4f));
    g_g2w[i] = (0.2989f * w0 + 0.587f * w1 + 0.114f * w2) * 255.0f;
    g_g1[i]  = (0.2989f * a0 + 0.587f * a1 + 0.114f * a2) * 255.0f;

    float v0 = samp(i1, bb), v1 = samp(i1 + HW, bb), v2 = samp(i1 + 2 * HW, bb);
    float c0 = i2[r], c1 = i2[HW + r], c2 = i2[2 * HW + r];
    float pbw = mbw * (__powf(fabsf(c0 - v0) + 0.01f, 0.4f)
                     + __powf(fabsf(c1 - v1) + 0.01f, 0.4f)
                     + __powf(fabsf(c2 - v2) + 0.01f, 0.4f));
    g_g1w[i] = (0.2989f * v0 + 0.587f * v1 + 0.114f * v2) * 255.0f;
    g_g2[i]  = (0.2989f * c0 + 0.587f * c1 + 0.114f * c2) * 255.0f;

    // block reduction: pfw, pbw, mfw, mbw
    float vals[4] = {pfw, pbw, mfw, mbw};
    __shared__ float red[8][4];
    int lane = threadIdx.x & 31, wid = threadIdx.x >> 5;
    #pragma unroll
    for (int k = 0; k < 4; k++) {
        float s = warp_reduce(vals[k]);
        if (lane == 0) red[wid][k] = s;
    }
    __syncthreads();
    if (threadIdx.x == 0) {
        float s0 = 0, s1 = 0, s2 = 0, s3 = 0;
        #pragma unroll
        for (int w = 0; w < 8; w++) { s0 += red[w][0]; s1 += red[w][1]; s2 += red[w][2]; s3 += red[w][3]; }
        atomicAdd(&g_acc[0], (double)s0);
        atomicAdd(&g_acc[1], (double)s1);
        atomicAdd(&g_acc[4], (double)s2);
        atomicAdd(&g_acc[5], (double)s3);
    }
}

// ---------------------------------------------------------------------------
// Census: round-7 tap math (proven best), 32x16 tile @ 512 threads
// (halo redundancy 2.08 -> 1.63 loads/pixel), finalize folded into the
// last-completing block (threadFenceReduction pattern) — no k_final launch.
// ---------------------------------------------------------------------------
constexpr int TX = 32, TY = 16;
constexpr int SW = TX + 6, SH = TY + 6;   // 38 x 22 value tile
constexpr int NCBLK = (W / TX) * (H / TY) * B;   // 4608 census blocks

__global__ void __launch_bounds__(512) k_census(const float* __restrict__ occ_fw,
                                                float* __restrict__ out) {
    __shared__ float2 vf[SH][SW];   // (g1, g2w)  forward pair
    __shared__ float2 vb[SH][SW];   // (g2, g1w)  backward pair
    __shared__ float2 red[16];
    __shared__ bool is_last;

    int b   = blockIdx.z;
    int bx0 = blockIdx.x * TX;
    int by0 = blockIdx.y * TY;
    const float* p1  = g_g1  + (size_t)b * HW;
    const float* p2w = g_g2w + (size_t)b * HW;
    const float* p2  = g_g2  + (size_t)b * HW;
    const float* p1w = g_g1w + (size_t)b * HW;

    int tid = threadIdx.y * TX + threadIdx.x;
    for (int t = tid; t < SH * SW; t += TX * TY) {
        int ly = t / SW, lx = t - ly * SW;
        int gy = by0 + ly - 3, gx = bx0 + lx - 3;
        float a = 0, bb = 0, c = 0, d = 0;
        if (gy >= 0 && gy < H && gx >= 0 && gx < W) {
            int gi = gy * W + gx;
            a = p1[gi]; bb = p2w[gi]; c = p2[gi]; d = p1w[gi];
        }
        vf[ly][lx] = make_float2(a, bb);
        vb[ly][lx] = make_float2(c, d);
    }
    __syncthreads();

    int lx = threadIdx.x, ly = threadIdx.y;
    float2 cf = vf[ly + 3][lx + 3];
    float2 cb = vb[ly + 3][lx + 3];

    float dsf = 0.0f, dsb = 0.0f;
    #pragma unroll
    for (int dy = 0; dy < 7; dy++) {
        #pragma unroll
        for (int dx = 0; dx < 7; dx++) {
            if (dy == 3 && dx == 3) continue;         // center tap == 0
            const bool NEWTON = ((dy * 7 + dx) % 3) == 0;   // 16 of 48 taps

            float2 nf = vf[ly + dy][lx + dx];
            float2 nb = vb[ly + dy][lx + dx];

            // pair fw: (img1, img2_warped)
            float d1 = nf.x - cf.x;
            float t1 = d1 * rsqrtf(fmaf(d1, d1, 0.81f));
            float d2 = nf.y - cf.y;
            float t2 = d2 * rsqrtf(fmaf(d2, d2, 0.81f));
            float df = t1 - t2;
            float dd = df * df;
            if (NEWTON) dsf += dd * rcp_fma(0.1f + dd);
            else        dsf += __fdividef(dd, 0.1f + dd);

            // pair bw: (img2, img1_warped)
            float e1 = nb.x - cb.x;
            float u1 = e1 * rsqrtf(fmaf(e1, e1, 0.81f));
            float e2 = nb.y - cb.y;
            float u2 = e2 * rsqrtf(fmaf(e2, e2, 0.81f));
            float db = u1 - u2;
            float ee = db * db;
            if (NEWTON) dsb += ee * rcp_fma(0.1f + ee);
            else        dsb += __fdividef(ee, 0.1f + ee);
        }
    }

    int gy = by0 + ly, gx = bx0 + lx;
    int i = b * HW + gy * W + gx;
    float maskf = 1.0f - occ_fw[i];
    float maskb = g_maskbw[i];
    float cfv = __powf(dsf + 0.01f, 0.4f) * maskf;
    float cbv = __powf(dsb + 0.01f, 0.4f) * maskb;

    int lane = tid & 31, wid = tid >> 5;
    float sf = warp_reduce(cfv);
    float sb = warp_reduce(cbv);
    if (lane == 0) red[wid] = make_float2(sf, sb);
    __syncthreads();
    if (tid == 0) {
        float a = 0, c = 0;
        #pragma unroll
        for (int w = 0; w < 16; w++) { a += red[w].x; c += red[w].y; }
        atomicAdd(&g_acc[2], (double)a);
        atomicAdd(&g_acc[3], (double)c);
        // signal completion; detect last block
        __threadfence();
        unsigned int old = atomicAdd(&g_ctr, 1u);
        is_last = (old == NCBLK - 1);
    }
    __syncthreads();

    // Last block finalizes (all other blocks' g_acc atomics are visible:
    // they fenced before incrementing the counter).
    if (is_last && tid == 0) {
        __threadfence();
        double dfw = g_acc[4] * 2.0 + 1e-6;
        double dbw = g_acc[5] * 2.0 + 1e-6;
        double photo  = g_acc[0] / dfw + g_acc[1] / dbw;
        double census = g_acc[2] / dfw + g_acc[3] / dbw;
        out[0] = (float)(photo + census);
        out[1] = (float)photo;
        out[2] = (float)census;
        // reset for the next graph replay (globals are zero-init at load;
        // every call funnels through exactly one last block)
        #pragma unroll
        for (int k = 0; k < 6; k++) g_acc[k] = 0.0;
        g_ctr = 0u;
    }
}

extern "C" void kernel_launch(void* const* d_in, const int* in_sizes, int n_in,
                              void* d_out, int out_size) {
    const float* img1 = (const float*)d_in[0];
    const float* img2 = (const float*)d_in[1];
    const float* ffw  = (const float*)d_in[2];
    const float* fbw  = (const float*)d_in[3];
    float* out = (float*)d_out;

    k_main<<<NPIX / 256, 256>>>(img1, img2, ffw, fbw, out);
    dim3 cg(W / TX, H / TY, B);
    dim3 cb(TX, TY, 1);
    k_census<<<cg, cb>>>(out + 3, out);
}

// round 15
// speedup vs baseline: 1.5361x; 1.5361x over previous
#include <cuda_runtime.h>
#include <math.h>

// Problem dims (fixed by setup_inputs)
constexpr int B = 8, H = 384, W = 768;
constexpr int HW = H * W;              // 294912
constexpr int NPIX = B * HW;           // 2359296

// Accumulators: 0 photo_fw, 1 photo_bw, 2 census_fw, 3 census_bw, 4 mask_fw_sum, 5 mask_bw_sum
// Zero-initialized at module load; the last census block re-zeroes after reading.
__device__ double g_acc[6];
__device__ unsigned int g_ctr;   // census block completion counter (zero-init)

// Scratch gray maps (intensity*255) and backward mask
__device__ float g_g1[NPIX];    // gray(img1)*255
__device__ float g_g2[NPIX];    // gray(img2)*255
__device__ float g_g1w[NPIX];   // gray(warp(img1, flow_bw))*255
__device__ float g_g2w[NPIX];   // gray(warp(img2, flow_fw))*255
__device__ float g_maskbw[NPIX];

struct Bilin {
    int i00, i01, i10, i11;
    float w00, w01, w10, w11;
};

__device__ __forceinline__ Bilin make_bilin(float fx, float fy, int x, int y) {
    float gx = fminf(fmaxf(fx + (float)x, 0.0f), (float)(W - 1));
    float gy = fminf(fmaxf(fy + (float)y, 0.0f), (float)(H - 1));
    float x0 = floorf(gx), y0 = floorf(gy);
    float wx = gx - x0, wy = gy - y0;
    int x0i = (int)x0, y0i = (int)y0;
    int x1i = min(x0i + 1, W - 1);
    int y1i = min(y0i + 1, H - 1);
    Bilin b;
    b.i00 = y0i * W + x0i;
    b.i01 = y0i * W + x1i;
    b.i10 = y1i * W + x0i;
    b.i11 = y1i * W + x1i;
    float ix = 1.0f - wx, iy = 1.0f - wy;
    b.w00 = ix * iy; b.w01 = wx * iy; b.w10 = ix * wy; b.w11 = wx * wy;
    return b;
}

__device__ __forceinline__ float samp(const float* __restrict__ p, const Bilin& bl) {
    return bl.w00 * __ldg(p + bl.i00) + bl.w01 * __ldg(p + bl.i01)
         + bl.w10 * __ldg(p + bl.i10) + bl.w11 * __ldg(p + bl.i11);
}

__device__ __forceinline__ float warp_reduce(float v) {
    #pragma unroll
    for (int o = 16; o > 0; o >>= 1) v += __shfl_down_sync(0xFFFFFFFFu, v, o);
    return v;
}

// FMA-pipe reciprocal: bit-hack seed + 2 Newton iterations.
// For x in (0.1, 5.1] rel err ~1e-6. Keeps the MUFU pipe free.
__device__ __forceinline__ float rcp_fma(float x) {
    float r = __uint_as_float(0x7EF477D5u - __float_as_uint(x));
    r = r * (2.0f - x * r);
    r = r * (2.0f - x * r);
    return r;
}

// Per-pixel: occ fw/bw, photometric loss partials, gray maps (round-7 form)
__global__ void __launch_bounds__(256) k_main(const float* __restrict__ img1,
                                              const float* __restrict__ img2,
                                              const float* __restrict__ ffw,
                                              const float* __restrict__ fbw,
                                              float* __restrict__ out) {
    int i = blockIdx.x * blockDim.x + threadIdx.x;   // grid sized exactly
    int b = i / HW;
    int r = i - b * HW;
    int y = r / W;
    int x = r - y * W;

    const float* f1 = ffw + (size_t)b * 2 * HW;
    const float* f2 = fbw + (size_t)b * 2 * HW;
    float fwx = f1[r],       fwy = f1[HW + r];
    float bwx = f2[r],       bwy = f2[HW + r];

    Bilin bf = make_bilin(fwx, fwy, x, y);
    Bilin bb = make_bilin(bwx, bwy, x, y);

    // occ_fw = compute_occ(flow_fw, flow_bw)
    float bwwx = samp(f2, bf);
    float bwwy = samp(f2 + HW, bf);
    float dx0 = fwx + bwwx, dy0 = fwy + bwwy;
    float mag = dx0 * dx0 + dy0 * dy0;
    float fm  = fwx * fwx + fwy * fwy + bwwx * bwwx + bwwy * bwwy;
    float occf = (mag > fmaf(0.01f, fm, 0.5f)) ? 1.0f : 0.0f;
    out[3 + i] = occf;
    float mfw = 1.0f - occf;

    // occ_bw = compute_occ(flow_bw, flow_fw)
    float fwwx = samp(f1, bb);
    float fwwy = samp(f1 + HW, bb);
    float dx1 = bwx + fwwx, dy1 = bwy + fwwy;
    float mag1 = dx1 * dx1 + dy1 * dy1;
    float fm1  = bwx * bwx + bwy * bwy + fwwx * fwwx + fwwy * fwwy;
    float occb = (mag1 > fmaf(0.01f, fm1, 0.5f)) ? 1.0f : 0.0f;
    float mbw = 1.0f - occb;
    g_maskbw[i] = mbw;

    // image warps + photometric
    const float* i1 = img1 + (size_t)b * 3 * HW;
    const float* i2 = img2 + (size_t)b * 3 * HW;

    float w0 = samp(i2, bf), w1 = samp(i2 + HW, bf), w2 = samp(i2 + 2 * HW, bf);
    float a0 = i1[r], a1 = i1[HW + r], a2 = i1[2 * HW + r];
    float pfw = mfw * (__powf(fabsf(a0 - w0) + 0.01f, 0.4f)
                     + __powf(fabsf(a1 - w1) + 0.01f, 0.4f)
                     + __powf(fabsf(a2 - w2) + 0.01f, 0.4f));
    g_g2w[i] = (0.2989f * w0 + 0.587f * w1 + 0.114f * w2) * 255.0f;
    g_g1[i]  = (0.2989f * a0 + 0.587f * a1 + 0.114f * a2) * 255.0f;

    float v0 = samp(i1, bb), v1 = samp(i1 + HW, bb), v2 = samp(i1 + 2 * HW, bb);
    float c0 = i2[r], c1 = i2[HW + r], c2 = i2[2 * HW + r];
    float pbw = mbw * (__powf(fabsf(c0 - v0) + 0.01f, 0.4f)
                     + __powf(fabsf(c1 - v1) + 0.01f, 0.4f)
                     + __powf(fabsf(c2 - v2) + 0.01f, 0.4f));
    g_g1w[i] = (0.2989f * v0 + 0.587f * v1 + 0.114f * v2) * 255.0f;
    g_g2[i]  = (0.2989f * c0 + 0.587f * c1 + 0.114f * c2) * 255.0f;

    // block reduction: pfw, pbw, mfw, mbw
    float vals[4] = {pfw, pbw, mfw, mbw};
    __shared__ float red[8][4];
    int lane = threadIdx.x & 31, wid = threadIdx.x >> 5;
    #pragma unroll
    for (int k = 0; k < 4; k++) {
        float s = warp_reduce(vals[k]);
        if (lane == 0) red[wid][k] = s;
    }
    __syncthreads();
    if (threadIdx.x == 0) {
        float s0 = 0, s1 = 0, s2 = 0, s3 = 0;
        #pragma unroll
        for (int w = 0; w < 8; w++) { s0 += red[w][0]; s1 += red[w][1]; s2 += red[w][2]; s3 += red[w][3]; }
        atomicAdd(&g_acc[0], (double)s0);
        atomicAdd(&g_acc[1], (double)s1);
        atomicAdd(&g_acc[4], (double)s2);
        atomicAdd(&g_acc[5], (double)s3);
    }
}

// ---------------------------------------------------------------------------
// Census: EXACT round-7 configuration (32x8 tile, 256 threads, 8 blocks/SM —
// this config is load-bearing: 512-thread variants lose full unroll and
// double the instruction count). Only change vs round 7: the finalize is
// folded into the last-completing block (threadFenceReduction pattern),
// removing the k_final launch tail.
// ---------------------------------------------------------------------------
constexpr int TX = 32, TY = 8;
constexpr int SW = TX + 6, SH = TY + 6;   // 38 x 14 value tile
constexpr int NCBLK = (W / TX) * (H / TY) * B;   // 9216 census blocks

__global__ void __launch_bounds__(256, 8) k_census(const float* __restrict__ occ_fw,
                                                   float* __restrict__ out) {
    __shared__ float2 vf[SH][SW];   // (g1, g2w)  forward pair
    __shared__ float2 vb[SH][SW];   // (g2, g1w)  backward pair
    __shared__ float2 red[8];
    __shared__ bool is_last;

    int b   = blockIdx.z;
    int bx0 = blockIdx.x * TX;
    int by0 = blockIdx.y * TY;
    const float* p1  = g_g1  + (size_t)b * HW;
    const float* p2w = g_g2w + (size_t)b * HW;
    const float* p2  = g_g2  + (size_t)b * HW;
    const float* p1w = g_g1w + (size_t)b * HW;

    int tid = threadIdx.y * TX + threadIdx.x;
    for (int t = tid; t < SH * SW; t += TX * TY) {
        int ly = t / SW, lx = t - ly * SW;
        int gy = by0 + ly - 3, gx = bx0 + lx - 3;
        float a = 0, bb = 0, c = 0, d = 0;
        if (gy >= 0 && gy < H && gx >= 0 && gx < W) {
            int gi = gy * W + gx;
            a = p1[gi]; bb = p2w[gi]; c = p2[gi]; d = p1w[gi];
        }
        vf[ly][lx] = make_float2(a, bb);
        vb[ly][lx] = make_float2(c, d);
    }
    __syncthreads();

    int lx = threadIdx.x, ly = threadIdx.y;
    float2 cf = vf[ly + 3][lx + 3];
    float2 cb = vb[ly + 3][lx + 3];

    float dsf = 0.0f, dsb = 0.0f;
    #pragma unroll
    for (int dy = 0; dy < 7; dy++) {
        #pragma unroll
        for (int dx = 0; dx < 7; dx++) {
            if (dy == 3 && dx == 3) continue;         // center tap == 0
            const bool NEWTON = ((dy * 7 + dx) % 3) == 0;   // 16 of 48 taps

            float2 nf = vf[ly + dy][lx + dx];
            float2 nb = vb[ly + dy][lx + dx];

            // pair fw: (img1, img2_warped)
            float d1 = nf.x - cf.x;
            float t1 = d1 * rsqrtf(fmaf(d1, d1, 0.81f));
            float d2 = nf.y - cf.y;
            float t2 = d2 * rsqrtf(fmaf(d2, d2, 0.81f));
            float df = t1 - t2;
            float dd = df * df;
            if (NEWTON) dsf += dd * rcp_fma(0.1f + dd);
            else        dsf += __fdividef(dd, 0.1f + dd);

            // pair bw: (img2, img1_warped)
            float e1 = nb.x - cb.x;
            float u1 = e1 * rsqrtf(fmaf(e1, e1, 0.81f));
            float e2 = nb.y - cb.y;
            float u2 = e2 * rsqrtf(fmaf(e2, e2, 0.81f));
            float db = u1 - u2;
            float ee = db * db;
            if (NEWTON) dsb += ee * rcp_fma(0.1f + ee);
            else        dsb += __fdividef(ee, 0.1f + ee);
        }
    }

    int gy = by0 + ly, gx = bx0 + lx;
    int i = b * HW + gy * W + gx;
    float maskf = 1.0f - occ_fw[i];
    float maskb = g_maskbw[i];
    float cfv = __powf(dsf + 0.01f, 0.4f) * maskf;
    float cbv = __powf(dsb + 0.01f, 0.4f) * maskb;

    int lane = tid & 31, wid = tid >> 5;
    float sf = warp_reduce(cfv);
    float sb = warp_reduce(cbv);
    if (lane == 0) red[wid] = make_float2(sf, sb);
    __syncthreads();
    if (tid == 0) {
        float a = 0, c = 0;
        #pragma unroll
        for (int w = 0; w < 8; w++) { a += red[w].x; c += red[w].y; }
        atomicAdd(&g_acc[2], (double)a);
        atomicAdd(&g_acc[3], (double)c);
        // signal completion; detect last block
        __threadfence();
        unsigned int old = atomicAdd(&g_ctr, 1u);
        is_last = (old == NCBLK - 1);
    }
    __syncthreads();

    // Last block finalizes (all other blocks' g_acc atomics are visible:
    // they fenced before incrementing the counter).
    if (is_last && tid == 0) {
        __threadfence();
        double dfw = g_acc[4] * 2.0 + 1e-6;
        double dbw = g_acc[5] * 2.0 + 1e-6;
        double photo  = g_acc[0] / dfw + g_acc[1] / dbw;
        double census = g_acc[2] / dfw + g_acc[3] / dbw;
        out[0] = (float)(photo + census);
        out[1] = (float)photo;
        out[2] = (float)census;
        // reset for the next graph replay (globals are zero-init at load;
        // every call funnels through exactly one last block)
        #pragma unroll
        for (int k = 0; k < 6; k++) g_acc[k] = 0.0;
        g_ctr = 0u;
    }
}

extern "C" void kernel_launch(void* const* d_in, const int* in_sizes, int n_in,
                              void* d_out, int out_size) {
    const float* img1 = (const float*)d_in[0];
    const float* img2 = (const float*)d_in[1];
    const float* ffw  = (const float*)d_in[2];
    const float* fbw  = (const float*)d_in[3];
    float* out = (float*)d_out;

    k_main<<<NPIX / 256, 256>>>(img1, img2, ffw, fbw, out);
    dim3 cg(W / TX, H / TY, B);
    dim3 cb(TX, TY, 1);
    k_census<<<cg, cb>>>(out + 3, out);
}